// round 4
// baseline (speedup 1.0000x reference)
#include <cuda_runtime.h>
#include <cstdint>

// Problem constants (fixed by the dataset)
#define NN   50000
#define DEG  16
#define FDIM 64
#define NE   (NN * DEG)   // 800000 edges

// Scratch (allocation-free rule: __device__ globals)
__device__ float g_T[NN * FDIM];   // x @ wm_top
__device__ float g_B[NN * FDIM];   // x @ wm_bot
__device__ float g_S[NN * FDIM];   // x_new @ weight_0
__device__ int   g_nbr[NE];        // converted int32 neighbor indices
__device__ int   g_is32 = 0;       // 1 if raw nbr buffer is int32, 0 if int64

// ---------------------------------------------------------------------------
// K0a: detect nbr dtype. If buffer is int64 (LE, values < 2^31), every odd
// int32 word is 0. If int32, odd words are random indices (some nonzero).
// Reading the first NE int32 words is in-bounds under both interpretations.
// Only SETS the flag (statically initialized to 0) — no reset, no race;
// input is constant across graph replays so the flag is deterministic.
// ---------------------------------------------------------------------------
__global__ void k_detect(const int* __restrict__ raw)
{
    int i = (blockIdx.x * blockDim.x + threadIdx.x) * 2 + 1;  // odd positions
    for (; i < NE; i += gridDim.x * blockDim.x * 2)
        if (raw[i] != 0) { atomicExch(&g_is32, 1); return; }
}

// K0b: materialize int32 indices either way.
__global__ void k_convert(const int* __restrict__ raw)
{
    const int is32 = g_is32;
    for (int i = blockIdx.x * blockDim.x + threadIdx.x; i < NE;
         i += gridDim.x * blockDim.x)
        g_nbr[i] = is32 ? raw[i] : raw[2 * i];   // lo word of int64
}

// ---------------------------------------------------------------------------
// K1: T = x @ wm_top ; B = x @ wm_bot   (wm = weights_mask0, [128 x 64])
// Warp-per-row; W tiles in shared; lane handles features (l, l+32).
// ---------------------------------------------------------------------------
__global__ void k_gemm_tb(const float* __restrict__ x,
                          const float* __restrict__ wm)
{
    __shared__ float sT[FDIM * FDIM];
    __shared__ float sB[FDIM * FDIM];
    __shared__ float sx[8][FDIM];

    const int tid = threadIdx.x;
    for (int i = tid; i < FDIM * FDIM; i += blockDim.x) {
        sT[i] = wm[i];
        sB[i] = wm[FDIM * FDIM + i];
    }
    __syncthreads();

    const int lane   = tid & 31;
    const int wsub   = tid >> 5;
    const int gw     = blockIdx.x * (blockDim.x >> 5) + wsub;
    const int nwarps = gridDim.x * (blockDim.x >> 5);

    for (int r = gw; r < NN; r += nwarps) {
        sx[wsub][lane]      = x[r * FDIM + lane];
        sx[wsub][lane + 32] = x[r * FDIM + lane + 32];
        __syncwarp();

        float t0 = 0.f, t1 = 0.f, b0 = 0.f, b1 = 0.f;
        #pragma unroll
        for (int k = 0; k < FDIM; k++) {
            const float xk = sx[wsub][k];
            t0 += xk * sT[k * FDIM + lane];
            t1 += xk * sT[k * FDIM + lane + 32];
            b0 += xk * sB[k * FDIM + lane];
            b1 += xk * sB[k * FDIM + lane + 32];
        }
        g_T[r * FDIM + lane]      = t0;
        g_T[r * FDIM + lane + 32] = t1;
        g_B[r * FDIM + lane]      = b0;
        g_B[r * FDIM + lane + 32] = b1;
        __syncwarp();
    }
}

// ---------------------------------------------------------------------------
// K2 (fused): x_new[n] = x[n] + sum_d sigmoid(T[n]+B[j]) * drop[n,d] * x[j]
//             S[n]     = x_new[n] @ weight_0
// Warp-per-node. drop_mask is the big stream (205 MB); x/B gathers hit L2.
// ---------------------------------------------------------------------------
__global__ void k_edge_support(const float* __restrict__ x,
                               const float* __restrict__ w0,
                               const float* __restrict__ drop)
{
    __shared__ float sW[FDIM * FDIM];
    __shared__ float sx[8][FDIM];

    const int tid = threadIdx.x;
    for (int i = tid; i < FDIM * FDIM; i += blockDim.x) sW[i] = w0[i];
    __syncthreads();

    const int lane   = tid & 31;
    const int wsub   = tid >> 5;
    const int gw     = blockIdx.x * (blockDim.x >> 5) + wsub;
    const int nwarps = gridDim.x * (blockDim.x >> 5);

    for (int n = gw; n < NN; n += nwarps) {
        const float t0 = g_T[n * FDIM + lane];
        const float t1 = g_T[n * FDIM + lane + 32];
        float a0 = x[n * FDIM + lane];
        float a1 = x[n * FDIM + lane + 32];

        const int*   nb = g_nbr + n * DEG;
        const float* dm = drop + (size_t)n * DEG * FDIM;

        #pragma unroll
        for (int d = 0; d < DEG; d++) {
            const int j = nb[d];                      // broadcast load
            const float b0  = g_B[j * FDIM + lane];
            const float b1  = g_B[j * FDIM + lane + 32];
            const float xj0 = x[j * FDIM + lane];
            const float xj1 = x[j * FDIM + lane + 32];
            const float m0  = dm[d * FDIM + lane];
            const float m1  = dm[d * FDIM + lane + 32];
            const float s0  = __fdividef(1.f, 1.f + __expf(-(t0 + b0)));
            const float s1  = __fdividef(1.f, 1.f + __expf(-(t1 + b1)));
            a0 += s0 * m0 * xj0;
            a1 += s1 * m1 * xj1;
        }

        // Fused support GEMM: S[n] = x_new @ weight_0
        sx[wsub][lane]      = a0;
        sx[wsub][lane + 32] = a1;
        __syncwarp();
        float o0 = 0.f, o1 = 0.f;
        #pragma unroll
        for (int k = 0; k < FDIM; k++) {
            const float xk = sx[wsub][k];
            o0 += xk * sW[k * FDIM + lane];
            o1 += xk * sW[k * FDIM + lane + 32];
        }
        g_S[n * FDIM + lane]      = o0;
        g_S[n * FDIM + lane + 32] = o1;
        __syncwarp();
    }
}

// ---------------------------------------------------------------------------
// K3: out[n] = bias + sum_d adj[n,d] * S[nbr[n,d]]
// ---------------------------------------------------------------------------
__global__ void k_out(const float* __restrict__ adj,
                      const float* __restrict__ bias,
                      float* __restrict__ out)
{
    const int tid    = threadIdx.x;
    const int lane   = tid & 31;
    const int gw     = blockIdx.x * (blockDim.x >> 5) + (tid >> 5);
    const int nwarps = gridDim.x * (blockDim.x >> 5);

    const float bi0 = bias[lane];
    const float bi1 = bias[lane + 32];

    for (int n = gw; n < NN; n += nwarps) {
        float o0 = bi0, o1 = bi1;
        const int*   nb = g_nbr + n * DEG;
        const float* av = adj + (size_t)n * DEG;
        #pragma unroll
        for (int d = 0; d < DEG; d++) {
            const int j = nb[d];
            const float a = av[d];
            o0 += a * g_S[j * FDIM + lane];
            o1 += a * g_S[j * FDIM + lane + 32];
        }
        out[n * FDIM + lane]      = o0;
        out[n * FDIM + lane + 32] = o1;
    }
}

// ---------------------------------------------------------------------------
// Inputs (metadata order): x, weight_0, weights_mask0, bias, adj_vals,
//                          drop_mask, nbr_idx (int32 or int64 — sniffed)
// ---------------------------------------------------------------------------
extern "C" void kernel_launch(void* const* d_in, const int* in_sizes, int n_in,
                              void* d_out, int out_size)
{
    const float* x    = (const float*)d_in[0];
    const float* w0   = (const float*)d_in[1];
    const float* wm   = (const float*)d_in[2];
    const float* bias = (const float*)d_in[3];
    const float* adj  = (const float*)d_in[4];
    const float* drop = (const float*)d_in[5];
    const int*   nbrr = (const int*)d_in[6];
    float* out = (float*)d_out;

    k_detect <<<148, 256>>>(nbrr);
    k_convert<<<148, 256>>>(nbrr);
    k_gemm_tb<<<592, 256>>>(x, wm);
    k_edge_support<<<592, 256>>>(x, w0, drop);
    k_out<<<592, 256>>>(adj, bias, out);
}

// round 5
// speedup vs baseline: 1.4124x; 1.4124x over previous
#include <cuda_runtime.h>
#include <cstdint>

// Problem constants (fixed by the dataset)
#define NN   50000
#define DEG  16
#define FDIM 64
#define NE   (NN * DEG)   // 800000 edges

// Scratch (allocation-free rule: __device__ globals). 16B-aligned for vector ld/st.
__device__ __align__(16) float g_T[NN * FDIM];   // x @ wm_top
__device__ __align__(16) float g_B[NN * FDIM];   // x @ wm_bot
__device__ __align__(16) float g_S[NN * FDIM];   // x_new @ weight_0
__device__ int   g_nbr[NE];
__device__ int   g_is32 = 0;       // 1 if raw nbr buffer is int32, 0 if int64

// Single-MUFU sigmoid: sigma(z) = 0.5*tanh(z/2) + 0.5
__device__ __forceinline__ float sigmoid_fast(float z)
{
    float t;
    asm("tanh.approx.f32 %0, %1;" : "=f"(t) : "f"(0.5f * z));
    return fmaf(0.5f, t, 0.5f);
}

// ---------------------------------------------------------------------------
// K0a: dtype sniff. int64 (LE, vals < 2^31) => all odd 32-bit words are 0.
// Scanning 2^18 words is conclusive (P[int32 gives all-zero] ~ (1/50000)^131072).
// Flag is set-only (statically 0) — deterministic, race-free.
// ---------------------------------------------------------------------------
__global__ void k_detect(const int* __restrict__ raw)
{
    int i = (blockIdx.x * blockDim.x + threadIdx.x) * 2 + 1;
    const int lim = NE < (1 << 18) ? NE : (1 << 18);
    for (; i < lim; i += gridDim.x * blockDim.x * 2)
        if (raw[i] != 0) { atomicExch(&g_is32, 1); return; }
}

// K0b: materialize int32 indices either way.
__global__ void k_convert(const int* __restrict__ raw)
{
    const int is32 = g_is32;
    for (int i = blockIdx.x * blockDim.x + threadIdx.x; i < NE;
         i += gridDim.x * blockDim.x)
        g_nbr[i] = is32 ? raw[i] : raw[2 * i];   // lo word of int64
}

// ---------------------------------------------------------------------------
// K1: T = x @ wm_top ; B = x @ wm_bot.  Warp-per-row, lane owns features
// (2l, 2l+1) -> all weight LDS and all global ld/st are 64-bit.
// ---------------------------------------------------------------------------
__global__ void k_gemm_tb(const float* __restrict__ x,
                          const float* __restrict__ wm)
{
    __shared__ float2 sT[FDIM * 32];   // [k][lane] = wm_top[k][2l..2l+1]
    __shared__ float2 sB[FDIM * 32];
    __shared__ float2 sx[8][32];

    const int tid = threadIdx.x;
    const float2* wm2 = (const float2*)wm;
    for (int i = tid; i < FDIM * 32; i += blockDim.x) {
        sT[i] = wm2[i];
        sB[i] = wm2[FDIM * 32 + i];
    }
    __syncthreads();

    const int lane   = tid & 31;
    const int wsub   = tid >> 5;
    const int gw     = blockIdx.x * (blockDim.x >> 5) + wsub;
    const int nwarps = gridDim.x * (blockDim.x >> 5);
    const float2* x2 = (const float2*)x;

    for (int r = gw; r < NN; r += nwarps) {
        sx[wsub][lane] = x2[r * 32 + lane];
        __syncwarp();

        float2 t = make_float2(0.f, 0.f);
        float2 b = make_float2(0.f, 0.f);
        const float* sxf = (const float*)sx[wsub];
        #pragma unroll
        for (int k = 0; k < FDIM; k++) {
            const float xk = sxf[k];
            const float2 wt = sT[k * 32 + lane];
            const float2 wb = sB[k * 32 + lane];
            t.x += xk * wt.x;  t.y += xk * wt.y;
            b.x += xk * wb.x;  b.y += xk * wb.y;
        }
        ((float2*)g_T)[r * 32 + lane] = t;
        ((float2*)g_B)[r * 32 + lane] = b;
        __syncwarp();
    }
}

// ---------------------------------------------------------------------------
// K2 (fused): x_new[n] = x[n] + sum_d sigmoid(T[n]+B[j]) * drop[n,d] * x[j]
//             S[n]     = x_new[n] @ weight_0
// Warp-per-node, float2 lanes, 128-reg budget for 16-deep gather MLP,
// streaming loads for the 205 MB drop_mask.
// ---------------------------------------------------------------------------
__global__ __launch_bounds__(256, 2)
void k_edge_support(const float* __restrict__ x,
                    const float* __restrict__ w0,
                    const float* __restrict__ drop)
{
    __shared__ float2 sW[FDIM * 32];   // [k][lane] = w0[k][2l..2l+1]
    __shared__ float2 sx[8][32];

    const int tid = threadIdx.x;
    const float2* w02 = (const float2*)w0;
    for (int i = tid; i < FDIM * 32; i += blockDim.x) sW[i] = w02[i];
    __syncthreads();

    const int lane   = tid & 31;
    const int wsub   = tid >> 5;
    const int gw     = blockIdx.x * (blockDim.x >> 5) + wsub;
    const int nwarps = gridDim.x * (blockDim.x >> 5);
    const float2* x2 = (const float2*)x;
    const float2* B2 = (const float2*)g_B;
    const float2* T2 = (const float2*)g_T;

    for (int n = gw; n < NN; n += nwarps) {
        const float2 t = T2[n * 32 + lane];
        float2 a = x2[n * 32 + lane];

        const int*    nb = g_nbr + n * DEG;
        const float2* dm = (const float2*)(drop + (size_t)n * DEG * FDIM);

        #pragma unroll
        for (int d = 0; d < DEG; d++) {
            const int j = nb[d];                       // broadcast load
            const float2 b  = B2[j * 32 + lane];
            const float2 xj = x2[j * 32 + lane];
            const float2 m  = __ldcs(dm + d * 32 + lane);   // pure stream
            const float s0 = sigmoid_fast(t.x + b.x);
            const float s1 = sigmoid_fast(t.y + b.y);
            a.x += s0 * m.x * xj.x;
            a.y += s1 * m.y * xj.y;
        }

        // Fused support GEMM: S[n] = x_new @ weight_0
        sx[wsub][lane] = a;
        __syncwarp();
        float2 o = make_float2(0.f, 0.f);
        const float* sxf = (const float*)sx[wsub];
        #pragma unroll
        for (int k = 0; k < FDIM; k++) {
            const float xk = sxf[k];
            const float2 w = sW[k * 32 + lane];
            o.x += xk * w.x;  o.y += xk * w.y;
        }
        ((float2*)g_S)[n * 32 + lane] = o;
        __syncwarp();
    }
}

// ---------------------------------------------------------------------------
// K3: out[n] = bias + sum_d adj[n,d] * S[nbr[n,d]]   (float2 gathers of g_S)
// ---------------------------------------------------------------------------
__global__ __launch_bounds__(256, 2)
void k_out(const float* __restrict__ adj,
           const float* __restrict__ bias,
           float* __restrict__ out)
{
    const int tid    = threadIdx.x;
    const int lane   = tid & 31;
    const int gw     = blockIdx.x * (blockDim.x >> 5) + (tid >> 5);
    const int nwarps = gridDim.x * (blockDim.x >> 5);

    const float2 bi = ((const float2*)bias)[lane];
    const float2* S2 = (const float2*)g_S;

    for (int n = gw; n < NN; n += nwarps) {
        float2 o = bi;
        const int*   nb = g_nbr + n * DEG;
        const float* av = adj + (size_t)n * DEG;
        #pragma unroll
        for (int d = 0; d < DEG; d++) {
            const int j   = nb[d];
            const float a = av[d];
            const float2 s = S2[j * 32 + lane];
            o.x += a * s.x;
            o.y += a * s.y;
        }
        ((float2*)out)[n * 32 + lane] = o;
    }
}

// ---------------------------------------------------------------------------
// Inputs (metadata order): x, weight_0, weights_mask0, bias, adj_vals,
//                          drop_mask, nbr_idx (int32 or int64 — sniffed)
// ---------------------------------------------------------------------------
extern "C" void kernel_launch(void* const* d_in, const int* in_sizes, int n_in,
                              void* d_out, int out_size)
{
    const float* x    = (const float*)d_in[0];
    const float* w0   = (const float*)d_in[1];
    const float* wm   = (const float*)d_in[2];
    const float* bias = (const float*)d_in[3];
    const float* adj  = (const float*)d_in[4];
    const float* drop = (const float*)d_in[5];
    const int*   nbrr = (const int*)d_in[6];
    float* out = (float*)d_out;

    k_detect <<<64, 256>>>(nbrr);
    k_convert<<<148, 256>>>(nbrr);
    k_gemm_tb<<<592, 256>>>(x, wm);
    k_edge_support<<<592, 256>>>(x, w0, drop);
    k_out<<<592, 256>>>(adj, bias, out);
}

// round 6
// speedup vs baseline: 1.9992x; 1.4154x over previous
#include <cuda_runtime.h>
#include <cstdint>
#include <cstring>

#define NN   50000
#define DEG  16
#define FDIM 64
#define NE   (NN * DEG)

// Scratch (allocation-free rule)
__device__ __align__(16) float g_T[NN * FDIM];
__device__ __align__(16) float g_B[NN * FDIM];
__device__ __align__(16) float g_xn[NN * FDIM];   // x_new
__device__ __align__(16) int   g_nbr[NE];
__device__ int g_is32 = 0;

// ---- packed f32x2 helpers (Blackwell) -------------------------------------
__device__ __forceinline__ unsigned long long pack2(float v) {
    unsigned long long r;
    asm("mov.b64 %0, {%1, %1};" : "=l"(r) : "f"(v));
    return r;
}
__device__ __forceinline__ void fma2(unsigned long long& d,
                                     unsigned long long a, unsigned long long b) {
    asm("fma.rn.f32x2 %0, %1, %2, %0;" : "+l"(d) : "l"(a), "l"(b));
}
__device__ __forceinline__ float2 unpack2(unsigned long long v) {
    float2 f;
    asm("mov.b64 {%0, %1}, %2;" : "=f"(f.x), "=f"(f.y) : "l"(v));
    return f;
}
__device__ __forceinline__ float sigmoid_fast(float z) {
    float t;
    asm("tanh.approx.f32 %0, %1;" : "=f"(t) : "f"(0.5f * z));
    return fmaf(0.5f, t, 0.5f);
}

// ---------------------------------------------------------------------------
// K0: dtype sniff + convert (int64 lo-words vs int32)
// ---------------------------------------------------------------------------
__global__ void k_detect(const int* __restrict__ raw)
{
    int i = (blockIdx.x * blockDim.x + threadIdx.x) * 2 + 1;
    const int lim = NE < (1 << 18) ? NE : (1 << 18);
    for (; i < lim; i += gridDim.x * blockDim.x * 2)
        if (raw[i] != 0) { atomicExch(&g_is32, 1); return; }
}
__global__ void k_convert(const int* __restrict__ raw)
{
    const int is32 = g_is32;
    for (int i = blockIdx.x * blockDim.x + threadIdx.x; i < NE;
         i += gridDim.x * blockDim.x)
        g_nbr[i] = is32 ? raw[i] : raw[2 * i];
}

// ---------------------------------------------------------------------------
// K1: T = x@wm_top, B = x@wm_bot.  8 rows/warp amortized weights, f32x2 FMA.
// Shared: sT+sB (32KB) + staged x rows (16KB) = 48KB exactly.
// ---------------------------------------------------------------------------
__global__ __launch_bounds__(256, 2)
void k_gemm_tb(const float* __restrict__ x, const float* __restrict__ wm)
{
    __shared__ float2 sT[FDIM * 32];
    __shared__ float2 sB[FDIM * 32];
    __shared__ float  sx[8][8][FDIM];     // [warp][row][k]

    const int tid = threadIdx.x;
    const float2* wm2 = (const float2*)wm;
    for (int i = tid; i < FDIM * 32; i += blockDim.x) {
        sT[i] = wm2[i];
        sB[i] = wm2[FDIM * 32 + i];
    }
    __syncthreads();

    const int lane = tid & 31, wsub = tid >> 5;
    const int gw = blockIdx.x * 8 + wsub;
    const int nwarps = gridDim.x * 8;
    const float2* x2 = (const float2*)x;

    for (int c = gw; c < NN / 8; c += nwarps) {
        const int base = c * 8;
        #pragma unroll
        for (int r = 0; r < 8; r++)
            ((float2*)sx[wsub][r])[lane] = x2[(base + r) * 32 + lane];
        __syncwarp();

        unsigned long long tA[8], bA[8];
        #pragma unroll
        for (int r = 0; r < 8; r++) { tA[r] = 0ull; bA[r] = 0ull; }

        #pragma unroll 8
        for (int k = 0; k < FDIM; k++) {
            unsigned long long wt, wb;
            memcpy(&wt, &sT[k * 32 + lane], 8);
            memcpy(&wb, &sB[k * 32 + lane], 8);
            #pragma unroll
            for (int r = 0; r < 8; r++) {
                const unsigned long long xk = pack2(sx[wsub][r][k]);
                fma2(tA[r], xk, wt);
                fma2(bA[r], xk, wb);
            }
        }
        #pragma unroll
        for (int r = 0; r < 8; r++) {
            ((float2*)g_T)[(base + r) * 32 + lane] = unpack2(tA[r]);
            ((float2*)g_B)[(base + r) * 32 + lane] = unpack2(bA[r]);
        }
        __syncwarp();
    }
}

// ---------------------------------------------------------------------------
// K2: x_new[n] = x[n] + sum_d sigmoid(T[n]+B[j])*drop[n,d]*x[j]
// Half-warp per node, float4 lanes (16 lanes x 16B). 2 nodes/warp.
// ---------------------------------------------------------------------------
__global__ __launch_bounds__(256, 2)
void k_edge(const float* __restrict__ x, const float* __restrict__ drop)
{
    const int tid  = threadIdx.x;
    const int lane = tid & 31;
    const int hl   = lane >> 4;          // which node of the pair
    const int fl   = lane & 15;          // float4 slot
    const int gw   = blockIdx.x * 8 + (tid >> 5);
    const int nwarps = gridDim.x * 8;

    const float4* x4 = (const float4*)x;
    const float4* B4 = (const float4*)g_B;
    const float4* T4 = (const float4*)g_T;

    for (int c = gw; c < NN / 2; c += nwarps) {
        const int n = c * 2 + hl;
        const float4 t = T4[n * 16 + fl];
        float4 a = x4[n * 16 + fl];

        int js[DEG];
        {
            const int4* nb4 = (const int4*)(g_nbr + n * DEG);
            #pragma unroll
            for (int q = 0; q < 4; q++) *(int4*)&js[q * 4] = nb4[q];
        }
        const float4* dm = (const float4*)(drop + (size_t)n * DEG * FDIM);

        #pragma unroll
        for (int d = 0; d < DEG; d++) {
            const int j = js[d];
            const float4 b  = B4[j * 16 + fl];
            const float4 xj = x4[j * 16 + fl];
            const float4 m  = __ldcs(dm + d * 16 + fl);
            a.x += sigmoid_fast(t.x + b.x) * m.x * xj.x;
            a.y += sigmoid_fast(t.y + b.y) * m.y * xj.y;
            a.z += sigmoid_fast(t.z + b.z) * m.z * xj.z;
            a.w += sigmoid_fast(t.w + b.w) * m.w * xj.w;
        }
        ((float4*)g_xn)[n * 16 + fl] = a;
    }
}

// ---------------------------------------------------------------------------
// K34 (fused): agg[n] = sum_d adj[n,d]*x_new[nbr[n,d]] staged into shared,
// then out = agg @ weight_0 + bias   (8 rows/warp, f32x2).
// ---------------------------------------------------------------------------
__global__ __launch_bounds__(256, 2)
void k_agg_gemm(const float* __restrict__ adj, const float* __restrict__ w0,
                const float* __restrict__ bias, float* __restrict__ out)
{
    __shared__ float2 sW[FDIM * 32];
    __shared__ float  sx[8][8][FDIM];

    const int tid = threadIdx.x;
    const float2* w02 = (const float2*)w0;
    for (int i = tid; i < FDIM * 32; i += blockDim.x) sW[i] = w02[i];
    __syncthreads();

    const int lane = tid & 31, wsub = tid >> 5;
    const int hl = lane >> 4, fl = lane & 15;
    const int gw = blockIdx.x * 8 + wsub;
    const int nwarps = gridDim.x * 8;

    const float4* Xn4 = (const float4*)g_xn;
    const float2  bi  = ((const float2*)bias)[lane];
    unsigned long long biP;
    memcpy(&biP, &bi, 8);

    for (int c = gw; c < NN / 8; c += nwarps) {
        const int base = c * 8;

        // Phase A: aggregate 8 nodes (2 per pass, half-warp each) into shared
        #pragma unroll
        for (int p = 0; p < 4; p++) {
            const int n = base + 2 * p + hl;
            float aj[DEG];
            int js[DEG];
            {
                const float4* a4 = (const float4*)(adj + (size_t)n * DEG);
                const int4* nb4 = (const int4*)(g_nbr + n * DEG);
                #pragma unroll
                for (int q = 0; q < 4; q++) {
                    *(float4*)&aj[q * 4] = a4[q];
                    *(int4*)&js[q * 4]   = nb4[q];
                }
            }
            float4 acc = make_float4(0.f, 0.f, 0.f, 0.f);
            #pragma unroll
            for (int d = 0; d < DEG; d++) {
                const float4 s = Xn4[js[d] * 16 + fl];
                acc.x += aj[d] * s.x;  acc.y += aj[d] * s.y;
                acc.z += aj[d] * s.z;  acc.w += aj[d] * s.w;
            }
            *(float4*)&sx[wsub][2 * p + hl][fl * 4] = acc;
        }
        __syncwarp();

        // Phase B: out rows = sx @ W0 + bias
        unsigned long long o[8];
        #pragma unroll
        for (int r = 0; r < 8; r++) o[r] = biP;

        #pragma unroll 8
        for (int k = 0; k < FDIM; k++) {
            unsigned long long wv;
            memcpy(&wv, &sW[k * 32 + lane], 8);
            #pragma unroll
            for (int r = 0; r < 8; r++)
                fma2(o[r], pack2(sx[wsub][r][k]), wv);
        }
        #pragma unroll
        for (int r = 0; r < 8; r++)
            ((float2*)out)[(base + r) * 32 + lane] = unpack2(o[r]);
        __syncwarp();
    }
}

// ---------------------------------------------------------------------------
extern "C" void kernel_launch(void* const* d_in, const int* in_sizes, int n_in,
                              void* d_out, int out_size)
{
    const float* x    = (const float*)d_in[0];
    const float* w0   = (const float*)d_in[1];
    const float* wm   = (const float*)d_in[2];
    const float* bias = (const float*)d_in[3];
    const float* adj  = (const float*)d_in[4];
    const float* drop = (const float*)d_in[5];
    const int*   nbrr = (const int*)d_in[6];
    float* out = (float*)d_out;

    k_detect  <<<64, 256>>>(nbrr);
    k_convert <<<148, 256>>>(nbrr);
    k_gemm_tb <<<296, 256>>>(x, wm);
    k_edge    <<<592, 256>>>(x, drop);
    k_agg_gemm<<<296, 256>>>(adj, w0, bias, out);
}